// round 10
// baseline (speedup 1.0000x reference)
#include <cuda_runtime.h>
#include <cuda_fp16.h>
#include <cstdint>
#include <cstddef>

// ---------------- problem constants ----------------
#define NPAR   4096
#define KCH    32
#define NEIGHD 128
#define FEATD  256
#define NROWS  (NPAR * KCH)        // 131072
#define H1D    512
#define H2D    512
#define H3D    256
#define INSTR  (NEIGHD + FEATD)    // 384

// output layout: [relative_points (NROWS*3) | h (NROWS*256) | cluster (NROWS)]
#define RP_OFF 0
#define H_OFF  ((size_t)NROWS * 3)
#define CL_OFF (H_OFF + (size_t)NROWS * H3D)

// ---------------- scratch (device globals) ----------------
__device__ float  g_F1[(size_t)NPAR * H1D];      // fp32, 8 MB
__device__ __half g_H1h[(size_t)NROWS * H1D];    // h1 fp16, 128 MB
__device__ __half g_H2h[(size_t)NROWS * H2D];    // h2 fp16, 128 MB
__device__ __half g_W2T[512 * 512];              // W2^T fp16 [n][k]
__device__ __half g_W3T[256 * 512];              // W3^T fp16 [n][k]

// ---------------- helpers ----------------
__device__ __forceinline__ uint32_t smem_u32(const void* p) {
    uint32_t a;
    asm("{ .reg .u64 t; cvta.to.shared.u64 t, %1; cvt.u32.u64 %0, t; }" : "=r"(a) : "l"(p));
    return a;
}
__device__ __forceinline__ void ldsm4(uint32_t r[4], uint32_t addr) {
    asm volatile("ldmatrix.sync.aligned.m8n8.x4.shared.b16 {%0,%1,%2,%3}, [%4];"
                 : "=r"(r[0]), "=r"(r[1]), "=r"(r[2]), "=r"(r[3]) : "r"(addr));
}
__device__ __forceinline__ void mma_f16(float c[4], const uint32_t a[4],
                                        uint32_t b0, uint32_t b1) {
    asm volatile("mma.sync.aligned.m16n8k16.row.col.f32.f16.f16.f32 "
                 "{%0,%1,%2,%3}, {%4,%5,%6,%7}, {%8,%9}, {%0,%1,%2,%3};"
                 : "+f"(c[0]), "+f"(c[1]), "+f"(c[2]), "+f"(c[3])
                 : "r"(a[0]), "r"(a[1]), "r"(a[2]), "r"(a[3]), "r"(b0), "r"(b1));
}
__device__ __forceinline__ void cp16(uint32_t s, const void* g) {
    asm volatile("cp.async.cg.shared.global [%0], [%1], 16;" :: "r"(s), "l"(g));
}
#define CP_COMMIT() asm volatile("cp.async.commit_group;" ::: "memory")
#define CP_WAIT1()  asm volatile("cp.async.wait_group 1;" ::: "memory")
#define CP_WAIT0()  asm volatile("cp.async.wait_group 0;" ::: "memory")

// ---------------- common tiling ----------------
#define KC    32
#define NCH   (H1D / KC)      // 16 chunks
#define LDT   80              // 32 halves = 64B padded to 80B; conflict-free ldsm

// ---------------- kernel 1: decoder GEMM ----------------
__global__ void k_dec(const float* __restrict__ inf, const float* __restrict__ Wd,
                      const float* __restrict__ bd, float* __restrict__ out_rp)
{
    __shared__ float s[NEIGHD];
    const int p = blockIdx.x;
    const int t = threadIdx.x;
    s[t] = inf[(size_t)p * INSTR + t];
    __syncthreads();
    if (t < 96) {
        float acc = bd[t];
#pragma unroll 8
        for (int k = 0; k < NEIGHD; ++k)
            acc = fmaf(s[k], Wd[k * 96 + t], acc);
        out_rp[(size_t)p * 96 + t] = acc;
    }
}

// ---------------- kernel 2: merged weight transpose + fp16 prep ----------------
__global__ void k_prep(const float* __restrict__ W2, const float* __restrict__ W3)
{
    const int idx = blockIdx.x * 256 + threadIdx.x;
    if (idx < 512 * 512) {
        const int n = idx >> 9, k = idx & 511;
        g_W2T[idx] = __float2half(W2[(size_t)k * H2D + n]);
    } else {
        const int i2 = idx - 512 * 512;      // < 256*512
        const int n = i2 >> 9, k = i2 & 511;
        g_W3T[i2] = __float2half(W3[(size_t)k * H3D + n]);
    }
}

// ---------------- kernel 3: F1 = features @ W1[0:256,:] + b1 (fp32 SIMT) ----
__global__ void k_f1(const float* __restrict__ inf, const float* __restrict__ W1,
                     const float* __restrict__ b1)
{
    __shared__ float As[16 * 132];
    __shared__ float Bs[16 * 128];
    const int tid  = threadIdx.x;
    const int bm   = blockIdx.x * 128;
    const int bn   = blockIdx.y * 128;
    const int arow = tid >> 2;
    const int acol = (tid & 3) * 4;
    const int brow = tid >> 5;
    const int bcol = (tid & 31) * 4;
    const int tr   = (tid >> 4) * 8;
    const int tc   = (tid & 15) * 8;

    float acc[8][8];
#pragma unroll
    for (int i = 0; i < 8; ++i)
#pragma unroll
        for (int j = 0; j < 8; ++j) acc[i][j] = 0.f;

    for (int kt = 0; kt < FEATD; kt += 16) {
#pragma unroll
        for (int s = 0; s < 2; ++s) {
            const int m = arow + s * 64;
            const float4 av = *(const float4*)&inf[(size_t)(bm + m) * INSTR + NEIGHD + kt + acol];
            As[(acol + 0) * 132 + m] = av.x;
            As[(acol + 1) * 132 + m] = av.y;
            As[(acol + 2) * 132 + m] = av.z;
            As[(acol + 3) * 132 + m] = av.w;
        }
#pragma unroll
        for (int s = 0; s < 2; ++s) {
            const int k = brow + s * 8;
            *(float4*)&Bs[k * 128 + bcol] =
                *(const float4*)&W1[(size_t)(kt + k) * H1D + bn + bcol];
        }
        __syncthreads();
#pragma unroll
        for (int k = 0; k < 16; ++k) {
            const float4 a0 = *(const float4*)&As[k * 132 + tr];
            const float4 a1 = *(const float4*)&As[k * 132 + tr + 4];
            const float4 b0 = *(const float4*)&Bs[k * 128 + tc];
            const float4 b1v = *(const float4*)&Bs[k * 128 + tc + 4];
            const float am[8] = {a0.x, a0.y, a0.z, a0.w, a1.x, a1.y, a1.z, a1.w};
            const float bnv[8] = {b0.x, b0.y, b0.z, b0.w, b1v.x, b1v.y, b1v.z, b1v.w};
#pragma unroll
            for (int i = 0; i < 8; ++i)
#pragma unroll
                for (int j = 0; j < 8; ++j)
                    acc[i][j] = fmaf(am[i], bnv[j], acc[i][j]);
        }
        __syncthreads();
    }
#pragma unroll
    for (int i = 0; i < 8; ++i) {
        const size_t row = (size_t)(bm + tr + i);
#pragma unroll
        for (int j = 0; j < 8; ++j)
            g_F1[row * H1D + bn + tc + j] = acc[i][j] + b1[bn + tc + j];
    }
}

// ---------------- kernel 4: materialize h1 (fp16) + cluster ----------------
// h1[r,k] = relu(F1[r>>5,k] + rp[r,0..2] . W1tail[k]); 1024 blocks x 128 rows.
__global__ void __launch_bounds__(256) k_h1(const float* __restrict__ rp,
                                            const float* __restrict__ W1,
                                            float* __restrict__ out_cl)
{
    __shared__ float w1t[3 * H1D];
    __shared__ float rps[128 * 3];
    const int tid   = threadIdx.x;
    const int rbase = blockIdx.x * 128;

    for (int i = tid; i < 3 * H1D; i += 256)
        w1t[i] = W1[(size_t)(FEATD + i / H1D) * H1D + (i % H1D)];
    for (int i = tid; i < 128 * 3; i += 256)
        rps[i] = rp[(size_t)rbase * 3 + i];
    __syncthreads();

#pragma unroll 1
    for (int it = 0; it < 32; ++it) {
        const int seg = it * 256 + tid;      // 0..8191
        const int row = seg >> 6;            // 0..127
        const int k0  = (seg & 63) * 8;
        const int parent = (rbase + row) >> 5;
        const float* f = &g_F1[(size_t)parent * H1D + k0];
        const float4 f0 = *(const float4*)f;
        const float4 f1 = *(const float4*)(f + 4);
        const float fv[8] = {f0.x, f0.y, f0.z, f0.w, f1.x, f1.y, f1.z, f1.w};
        const float r0 = rps[row * 3 + 0];
        const float r1 = rps[row * 3 + 1];
        const float r2 = rps[row * 3 + 2];
        uint32_t u[4];
#pragma unroll
        for (int j = 0; j < 4; ++j) {
            const int k = k0 + 2 * j;
            const float v0 = fmaxf(fv[2*j]   + r0 * w1t[k]   + r1 * w1t[512 + k]   + r2 * w1t[1024 + k],   0.f);
            const float v1 = fmaxf(fv[2*j+1] + r0 * w1t[k+1] + r1 * w1t[512 + k+1] + r2 * w1t[1024 + k+1], 0.f);
            const __half2 h2v = __floats2half2_rn(v0, v1);
            u[j] = *(const uint32_t*)&h2v;
        }
        *(uint4*)&g_H1h[(size_t)(rbase + row) * H1D + k0] = make_uint4(u[0], u[1], u[2], u[3]);
    }
    for (int i = tid; i < 128; i += 256)
        out_cl[rbase + i] = (float)((rbase + i) >> 5);
}

// =======================================================================
// Pure cp.async double-buffered fp16 GEMM template; 512 threads, occ 1.
// MODE 0 (L2): CTA  64x512, A = g_H1h, B = g_W2T, out = g_H2h fp16 + relu.
// MODE 1 (L3): CTA 128x256, A = g_H2h, B = g_W3T, out = fp32 + relu.
// 3-stage ring (A+B per stage), prefetch depth 2; 16 warps, 32x64 per warp.
// =======================================================================
template<int MODE>
__global__ void __launch_bounds__(512, 1) k_gemm(
    const float* __restrict__ bias, float* __restrict__ outf)
{
    constexpr int MT   = MODE ? 128 : 64;
    constexpr int NT   = MODE ? 256 : 512;
    constexpr int STG  = (MT + NT) * LDT;   // A tile then B tile
    extern __shared__ char smem[];
    const uint32_t su = smem_u32(smem);
    const int tid  = threadIdx.x;
    const int wid  = tid >> 5;
    const int lane = tid & 31;
    const int bm   = blockIdx.x * MT;

    const __half* Asrc = MODE ? g_H2h : g_H1h;
    const __half* Bsrc = MODE ? g_W3T : g_W2T;

    const int warpM = MODE ? (wid & 3) : (wid & 1);
    const int warpN = MODE ? (wid >> 2) : (wid >> 1);
    const int a_row   = warpM * 32 + (lane & 15);
    const int a_kofs  = (lane >> 4) * 8;
    const int b_rbase = warpN * 64 + (lane & 7) + ((lane >> 4) << 3);
    const int b_kofs  = ((lane >> 3) & 1) * 8;

    auto issue = [&](int c) {
        const int kt = c * KC;
        const uint32_t stg = su + (c % 3) * STG;
        if (MODE == 1) {
            // A: 128 rows x 32 k -> 512 cp16, one per thread
            const int ar = tid >> 2, ak = (tid & 3) * 8;
            cp16(stg + ar * LDT + ak * 2, Asrc + (size_t)(bm + ar) * 512 + kt + ak);
            // B: 256 rows x 32 k -> 2 cp16 per thread
            const int br = tid >> 1, bk = (tid & 1) * 16;
            const __half* gb = Bsrc + (size_t)br * 512 + kt + bk;
            const uint32_t sb = stg + MT * LDT + br * LDT + bk * 2;
            cp16(sb, gb);
            cp16(sb + 16, gb + 8);
        } else {
            // A: 64 rows x 32 k -> 256 cp16 (threads 0..255)
            if (tid < 256) {
                const int ar = tid >> 2, ak = (tid & 3) * 8;
                cp16(stg + ar * LDT + ak * 2, Asrc + (size_t)(bm + ar) * 512 + kt + ak);
            }
            // B: 512 rows x 32 k -> 4 cp16 per thread (one row each)
            const __half* gb = Bsrc + (size_t)tid * 512 + kt;
            const uint32_t sb = stg + MT * LDT + tid * LDT;
            cp16(sb,      gb);
            cp16(sb + 16, gb + 8);
            cp16(sb + 32, gb + 16);
            cp16(sb + 48, gb + 24);
        }
        CP_COMMIT();
    };

    float acc[2][8][4];
#pragma unroll
    for (int i = 0; i < 2; ++i)
#pragma unroll
        for (int j = 0; j < 8; ++j)
#pragma unroll
            for (int q = 0; q < 4; ++q) acc[i][j][q] = 0.f;

    issue(0);
    issue(1);

#pragma unroll 1
    for (int c = 0; c < NCH; ++c) {
        CP_WAIT1();
        __syncthreads();
        if (c + 2 < NCH) issue(c + 2);

        const uint32_t abase = su + (c % 3) * STG;
        const uint32_t bbase = abase + MT * LDT;
#pragma unroll
        for (int ks = 0; ks < 2; ++ks) {
            const int kk = ks * 16;
            uint32_t ah[2][4];
#pragma unroll
            for (int mb = 0; mb < 2; ++mb)
                ldsm4(ah[mb], abase + (uint32_t)((a_row + mb * 16) * LDT + (kk + a_kofs) * 2));
#pragma unroll
            for (int np = 0; np < 4; ++np) {
                uint32_t bh[4];
                ldsm4(bh, bbase + (uint32_t)((b_rbase + np * 16) * LDT + (kk + b_kofs) * 2));
#pragma unroll
                for (int mb = 0; mb < 2; ++mb)
#pragma unroll
                    for (int ns = 0; ns < 2; ++ns)
                        mma_f16(acc[mb][np * 2 + ns], ah[mb], bh[2 * ns], bh[2 * ns + 1]);
            }
        }
    }
    CP_WAIT0();

    // ---- epilogue ----
    const int g   = lane >> 2;
    const int tig = lane & 3;
#pragma unroll
    for (int mb = 0; mb < 2; ++mb)
#pragma unroll
        for (int nb = 0; nb < 8; ++nb) {
            const int col = warpN * 64 + nb * 8 + tig * 2;   // NT == full output width
            const float bz0 = bias[col], bz1 = bias[col + 1];
            const int rr = bm + warpM * 32 + mb * 16 + g;
            const float* cc = acc[mb][nb];
#pragma unroll
            for (int hf = 0; hf < 2; ++hf) {
                const int r = rr + hf * 8;
                const float h0 = fmaxf(cc[2 * hf + 0] + bz0, 0.f);
                const float h1 = fmaxf(cc[2 * hf + 1] + bz1, 0.f);
                if (MODE == 0) {
                    *(__half2*)&g_H2h[(size_t)r * H2D + col] =
                        __halves2half2(__float2half(h0), __float2half(h1));
                } else {
                    *(float2*)&outf[(size_t)r * H3D + col] = make_float2(h0, h1);
                }
            }
        }
}

// ---------------- launch ----------------
extern "C" void kernel_launch(void* const* d_in, const int* in_sizes, int n_in,
                              void* d_out, int out_size)
{
    const float* inf = (const float*)d_in[0];
    const float* Wd  = (const float*)d_in[1];
    const float* bd  = (const float*)d_in[2];
    const float* W1  = (const float*)d_in[3];
    const float* b1  = (const float*)d_in[4];
    const float* W2  = (const float*)d_in[5];
    const float* b2  = (const float*)d_in[6];
    const float* W3  = (const float*)d_in[7];
    const float* b3  = (const float*)d_in[8];
    float* out = (float*)d_out;

    constexpr int SM0 = (64 + 512) * LDT * 3;    // 138240
    constexpr int SM1 = (128 + 256) * LDT * 3;   // 92160
    cudaFuncSetAttribute(k_gemm<0>, cudaFuncAttributeMaxDynamicSharedMemorySize, SM0);
    cudaFuncSetAttribute(k_gemm<1>, cudaFuncAttributeMaxDynamicSharedMemorySize, SM1);

    k_dec<<<NPAR, 128>>>(inf, Wd, bd, out + RP_OFF);
    k_prep<<<(512 * 512 + 256 * 512) / 256, 256>>>(W2, W3);
    k_f1<<<dim3(NPAR / 128, H1D / 128), 256>>>(inf, W1, b1);
    k_h1<<<NROWS / 128, 256>>>(out + RP_OFF, W1, out + CL_OFF);
    k_gemm<0><<<NROWS / 64, 512, SM0>>>(b2, nullptr);
    k_gemm<1><<<NROWS / 128, 512, SM1>>>(b3, out + H_OFF);
}

// round 11
// speedup vs baseline: 1.1423x; 1.1423x over previous
#include <cuda_runtime.h>
#include <cuda_fp16.h>
#include <cstdint>
#include <cstddef>

// ---------------- problem constants ----------------
#define NPAR   4096
#define KCH    32
#define NEIGHD 128
#define FEATD  256
#define NROWS  (NPAR * KCH)        // 131072
#define H1D    512
#define H2D    512
#define H3D    256
#define INSTR  (NEIGHD + FEATD)    // 384

// output layout: [relative_points (NROWS*3) | h (NROWS*256) | cluster (NROWS)]
#define RP_OFF 0
#define H_OFF  ((size_t)NROWS * 3)
#define CL_OFF (H_OFF + (size_t)NROWS * H3D)

// ---------------- scratch (device globals) ----------------
__device__ float  g_F1[(size_t)NPAR * H1D];      // fp32, 8 MB
__device__ __half g_H2h[(size_t)NROWS * H2D];    // h2 fp16, 128 MB
__device__ __half g_W2T[512 * 512];              // W2^T fp16 [n][k]
__device__ __half g_W3T[256 * 512];              // W3^T fp16 [n][k]

// ---------------- helpers ----------------
__device__ __forceinline__ uint32_t smem_u32(const void* p) {
    uint32_t a;
    asm("{ .reg .u64 t; cvta.to.shared.u64 t, %1; cvt.u32.u64 %0, t; }" : "=r"(a) : "l"(p));
    return a;
}
__device__ __forceinline__ void ldsm4(uint32_t r[4], uint32_t addr) {
    asm volatile("ldmatrix.sync.aligned.m8n8.x4.shared.b16 {%0,%1,%2,%3}, [%4];"
                 : "=r"(r[0]), "=r"(r[1]), "=r"(r[2]), "=r"(r[3]) : "r"(addr));
}
__device__ __forceinline__ void mma_f16(float c[4], const uint32_t a[4],
                                        uint32_t b0, uint32_t b1) {
    asm volatile("mma.sync.aligned.m16n8k16.row.col.f32.f16.f16.f32 "
                 "{%0,%1,%2,%3}, {%4,%5,%6,%7}, {%8,%9}, {%0,%1,%2,%3};"
                 : "+f"(c[0]), "+f"(c[1]), "+f"(c[2]), "+f"(c[3])
                 : "r"(a[0]), "r"(a[1]), "r"(a[2]), "r"(a[3]), "r"(b0), "r"(b1));
}
__device__ __forceinline__ void cp16(uint32_t s, const void* g) {
    asm volatile("cp.async.cg.shared.global [%0], [%1], 16;" :: "r"(s), "l"(g));
}
#define CP_COMMIT() asm volatile("cp.async.commit_group;" ::: "memory")
#define CP_WAIT1()  asm volatile("cp.async.wait_group 1;" ::: "memory")
#define CP_WAIT0()  asm volatile("cp.async.wait_group 0;" ::: "memory")

// ---------------- tiling ----------------
// k_mlp2: kc=64, 8 chunks, LDT6=144 (64 halves=128B pad to 144; conflict-free).
// k_mlp3: kc=32, 16 chunks, LDT=80.
#define KC6   64
#define NCH6  (H1D / KC6)     // 8
#define LDT6  144
#define KC    32
#define NCH   (H1D / KC)      // 16
#define LDT   80

// k_mlp2 SMEM: A dbuf 2 x (128*144); B ring 3 x (256*144); w1t; rps.
#define M0_ABUF   (128 * LDT6)                 // 18432
#define M0_BSTG   (256 * LDT6)                 // 36864
#define M0_OFF_A  0
#define M0_OFF_B  (2 * M0_ABUF)                // 36864
#define M0_OFF_W1 (M0_OFF_B + 3 * M0_BSTG)     // 147456
#define M0_OFF_RP (M0_OFF_W1 + 6144)           // 153600
#define M0_SMEM   (M0_OFF_RP + 1536)           // 155136

// k_mlp3 SMEM: ring 3 stages of (A 128*80 + B 128*80), occ 2.
#define M1_STG    (2 * 128 * LDT)              // 20480
#define M1_SMEM   (3 * M1_STG)                 // 61440

// ---------------- kernel: decoder GEMM ----------------
__global__ void k_dec(const float* __restrict__ inf, const float* __restrict__ Wd,
                      const float* __restrict__ bd, float* __restrict__ out_rp)
{
    __shared__ float s[NEIGHD];
    const int p = blockIdx.x;
    const int t = threadIdx.x;
    s[t] = inf[(size_t)p * INSTR + t];
    __syncthreads();
    if (t < 96) {
        float acc = bd[t];
#pragma unroll 8
        for (int k = 0; k < NEIGHD; ++k)
            acc = fmaf(s[k], Wd[k * 96 + t], acc);
        out_rp[(size_t)p * 96 + t] = acc;
    }
}

// ---------------- kernel: merged weight transpose + fp16 prep ----------------
__global__ void k_prep(const float* __restrict__ W2, const float* __restrict__ W3)
{
    const int idx = blockIdx.x * 256 + threadIdx.x;
    if (idx < 512 * 512) {
        const int n = idx >> 9, k = idx & 511;
        g_W2T[idx] = __float2half(W2[(size_t)k * H2D + n]);
    } else {
        const int i2 = idx - 512 * 512;
        const int n = i2 >> 9, k = i2 & 511;
        g_W3T[i2] = __float2half(W3[(size_t)k * H3D + n]);
    }
}

// ---------------- kernel: F1 = features @ W1[0:256,:] + b1 (fp32 SIMT) ----
__global__ void k_f1(const float* __restrict__ inf, const float* __restrict__ W1,
                     const float* __restrict__ b1)
{
    __shared__ float As[16 * 132];
    __shared__ float Bs[16 * 128];
    const int tid  = threadIdx.x;
    const int bm   = blockIdx.x * 128;
    const int bn   = blockIdx.y * 128;
    const int arow = tid >> 2;
    const int acol = (tid & 3) * 4;
    const int brow = tid >> 5;
    const int bcol = (tid & 31) * 4;
    const int tr   = (tid >> 4) * 8;
    const int tc   = (tid & 15) * 8;

    float acc[8][8];
#pragma unroll
    for (int i = 0; i < 8; ++i)
#pragma unroll
        for (int j = 0; j < 8; ++j) acc[i][j] = 0.f;

    for (int kt = 0; kt < FEATD; kt += 16) {
#pragma unroll
        for (int s = 0; s < 2; ++s) {
            const int m = arow + s * 64;
            const float4 av = *(const float4*)&inf[(size_t)(bm + m) * INSTR + NEIGHD + kt + acol];
            As[(acol + 0) * 132 + m] = av.x;
            As[(acol + 1) * 132 + m] = av.y;
            As[(acol + 2) * 132 + m] = av.z;
            As[(acol + 3) * 132 + m] = av.w;
        }
#pragma unroll
        for (int s = 0; s < 2; ++s) {
            const int k = brow + s * 8;
            *(float4*)&Bs[k * 128 + bcol] =
                *(const float4*)&W1[(size_t)(kt + k) * H1D + bn + bcol];
        }
        __syncthreads();
#pragma unroll
        for (int k = 0; k < 16; ++k) {
            const float4 a0 = *(const float4*)&As[k * 132 + tr];
            const float4 a1 = *(const float4*)&As[k * 132 + tr + 4];
            const float4 b0 = *(const float4*)&Bs[k * 128 + tc];
            const float4 b1v = *(const float4*)&Bs[k * 128 + tc + 4];
            const float am[8] = {a0.x, a0.y, a0.z, a0.w, a1.x, a1.y, a1.z, a1.w};
            const float bnv[8] = {b0.x, b0.y, b0.z, b0.w, b1v.x, b1v.y, b1v.z, b1v.w};
#pragma unroll
            for (int i = 0; i < 8; ++i)
#pragma unroll
                for (int j = 0; j < 8; ++j)
                    acc[i][j] = fmaf(am[i], bnv[j], acc[i][j]);
        }
        __syncthreads();
    }
#pragma unroll
    for (int i = 0; i < 8; ++i) {
        const size_t row = (size_t)(bm + tr + i);
#pragma unroll
        for (int j = 0; j < 8; ++j)
            g_F1[row * H1D + bn + tc + j] = acc[i][j] + b1[bn + tc + j];
    }
}

// ---------------- kernel: cluster indices ----------------
__global__ void k_cluster(float* __restrict__ out_cl)
{
    const int i = blockIdx.x * blockDim.x + threadIdx.x;
    if (i < NROWS) out_cl[i] = (float)(i >> 5);
}

// =======================================================================
// L2 GEMM (h2 = relu(h1 @ W2T + b2)): CTA 128x256, 512 threads, occ 1.
// kc=64: 8 chunks, one barrier pair per chunk, 64 MMA/warp between syncs.
// A = relu(F1[parent] + rp.W1tail) fp16 staged in SMEM (F1 L2-resident,
// loaded directly in stageA); B = W2T via cp.async 3-stage ring, depth 2.
// 16 warps: warpM = wid&3 (32 rows), warpN = wid>>2 (64 cols).
// =======================================================================
__global__ void __launch_bounds__(512, 1) k_mlp2(
    const float* __restrict__ rp, const float* __restrict__ W1,
    const float* __restrict__ b2)
{
    extern __shared__ char smem[];
    const uint32_t su = smem_u32(smem);
    const int tid  = threadIdx.x;
    const int wid  = tid >> 5;
    const int lane = tid & 31;
    const int bm   = blockIdx.x * 128;
    const int bn   = blockIdx.y * 256;

    float* w1t = (float*)(smem + M0_OFF_W1);
    float* rps = (float*)(smem + M0_OFF_RP);
    for (int i = tid; i < 3 * H1D; i += 512)
        w1t[i] = W1[(size_t)(FEATD + i / H1D) * H1D + (i % H1D)];
    for (int i = tid; i < 128 * 3; i += 512)
        rps[i] = rp[(size_t)bm * 3 + i];
    __syncthreads();

    const int warpM = wid & 3;
    const int warpN = wid >> 2;
    const int a_row   = warpM * 32 + (lane & 15);
    const int a_kofs  = (lane >> 4) * 8;
    const int b_rbase = warpN * 64 + (lane & 7) + ((lane >> 4) << 3);
    const int b_kofs  = ((lane >> 3) & 1) * 8;

    // A staging: 128 rows x 64 k per chunk; 4 threads/row, 16 elems each.
    const int prow = tid >> 2;             // 0..127
    const int pc0  = (tid & 3) * 16;       // 0,16,32,48
    const int parent = (bm + prow) >> 5;
    const float r0 = rps[prow * 3 + 0];
    const float r1 = rps[prow * 3 + 1];
    const float r2 = rps[prow * 3 + 2];

    // B staging: 256 rows x 64 k; 2 threads/row, 32 halves (4 cp16) each.
    const int brow = tid >> 1;             // 0..255
    const int bk0  = (tid & 1) * 32;       // halves

    auto stageA = [&](int c, int buf) {
        const int ktk = c * KC6 + pc0;
        const float* f = &g_F1[(size_t)parent * H1D + ktk];
        const float4 f0 = *(const float4*)f;
        const float4 f1v = *(const float4*)(f + 4);
        const float4 f2 = *(const float4*)(f + 8);
        const float4 f3 = *(const float4*)(f + 12);
        const float fv[16] = {f0.x, f0.y, f0.z, f0.w, f1v.x, f1v.y, f1v.z, f1v.w,
                              f2.x, f2.y, f2.z, f2.w, f3.x, f3.y, f3.z, f3.w};
        uint32_t uh[8];
#pragma unroll
        for (int j = 0; j < 8; ++j) {
            const int k = ktk + 2 * j;
            const float v0 = fmaxf(fv[2*j]   + r0 * w1t[k]   + r1 * w1t[512 + k]   + r2 * w1t[1024 + k],   0.f);
            const float v1 = fmaxf(fv[2*j+1] + r0 * w1t[k+1] + r1 * w1t[512 + k+1] + r2 * w1t[1024 + k+1], 0.f);
            const __half2 h2v = __floats2half2_rn(v0, v1);
            uh[j] = *(const uint32_t*)&h2v;
        }
        char* dst = smem + M0_OFF_A + buf * M0_ABUF + prow * LDT6 + pc0 * 2;
        *(uint4*)dst        = make_uint4(uh[0], uh[1], uh[2], uh[3]);
        *(uint4*)(dst + 16) = make_uint4(uh[4], uh[5], uh[6], uh[7]);
    };
    auto issueB = [&](int c) {
        const __half* g = &g_W2T[(size_t)(bn + brow) * 512 + c * KC6 + bk0];
        const uint32_t s = su + M0_OFF_B + (c % 3) * M0_BSTG + brow * LDT6 + bk0 * 2;
        cp16(s,      g);
        cp16(s + 16, g + 8);
        cp16(s + 32, g + 16);
        cp16(s + 48, g + 24);
        CP_COMMIT();
    };

    float acc[2][8][4];
#pragma unroll
    for (int i = 0; i < 2; ++i)
#pragma unroll
        for (int j = 0; j < 8; ++j)
#pragma unroll
            for (int q = 0; q < 4; ++q) acc[i][j][q] = 0.f;

    stageA(0, 0);
    issueB(0);
    issueB(1);

#pragma unroll 1
    for (int c = 0; c < NCH6; ++c) {
        CP_WAIT1();
        __syncthreads();                   // B(c) landed; A buf(c&1) staged
        if (c + 2 < NCH6) issueB(c + 2);

        const uint32_t abase = su + M0_OFF_A + (c & 1) * M0_ABUF;
        const uint32_t bbase = su + M0_OFF_B + (c % 3) * M0_BSTG;
#pragma unroll
        for (int ks = 0; ks < 4; ++ks) {
            const int kk = ks * 16;
            uint32_t ah[2][4];
#pragma unroll
            for (int mb = 0; mb < 2; ++mb)
                ldsm4(ah[mb], abase + (uint32_t)((a_row + mb * 16) * LDT6 + (kk + a_kofs) * 2));
#pragma unroll
            for (int np = 0; np < 4; ++np) {
                uint32_t bh[4];
                ldsm4(bh, bbase + (uint32_t)((b_rbase + np * 16) * LDT6 + (kk + b_kofs) * 2));
#pragma unroll
                for (int mb = 0; mb < 2; ++mb)
#pragma unroll
                    for (int ns = 0; ns < 2; ++ns)
                        mma_f16(acc[mb][np * 2 + ns], ah[mb], bh[2 * ns], bh[2 * ns + 1]);
            }
        }
        if (c + 1 < NCH6) stageA(c + 1, (c + 1) & 1);
    }
    CP_WAIT0();

    // epilogue -> g_H2h fp16
    const int g   = lane >> 2;
    const int tig = lane & 3;
#pragma unroll
    for (int mb = 0; mb < 2; ++mb)
#pragma unroll
        for (int nb = 0; nb < 8; ++nb) {
            const int col = bn + warpN * 64 + nb * 8 + tig * 2;
            const float bz0 = b2[col], bz1 = b2[col + 1];
            const int rr = bm + warpM * 32 + mb * 16 + g;
            const float* cc = acc[mb][nb];
#pragma unroll
            for (int hf = 0; hf < 2; ++hf) {
                const int r = rr + hf * 8;
                *(__half2*)&g_H2h[(size_t)r * H2D + col] =
                    __halves2half2(__float2half(fmaxf(cc[2*hf] + bz0, 0.f)),
                                   __float2half(fmaxf(cc[2*hf+1] + bz1, 0.f)));
            }
        }
}

// =======================================================================
// L3 GEMM (h = relu(h2 @ W3T + b3)): CTA 128x128, 256 threads, occ 2.
// A (g_H2h) and B (g_W3T) both via cp.async 3-stage ring, depth 2. (R8)
// =======================================================================
__global__ void __launch_bounds__(256, 2) k_mlp3(
    const float* __restrict__ b3, float* __restrict__ outf)
{
    extern __shared__ char smem[];
    const uint32_t su = smem_u32(smem);
    const int tid  = threadIdx.x;
    const int wid  = tid >> 5;
    const int lane = tid & 31;
    const int bm   = blockIdx.x * 128;
    const int bn   = blockIdx.y * 128;

    const int warpM = wid & 3;
    const int warpN = wid >> 2;
    const int a_row   = warpM * 32 + (lane & 15);
    const int a_kofs  = (lane >> 4) * 8;
    const int b_rbase = warpN * 64 + (lane & 7) + ((lane >> 4) << 3);
    const int b_kofs  = ((lane >> 3) & 1) * 8;

    const int prow = tid >> 1;
    const int kseg = (tid & 1) * 16;

    auto issue = [&](int c) {
        const int kt = c * KC;
        const uint32_t stg = su + (c % 3) * M1_STG;
        const __half* ga = &g_H2h[(size_t)(bm + prow) * H2D + kt + kseg];
        const uint32_t sa = stg + prow * LDT + kseg * 2;
        cp16(sa, ga);
        cp16(sa + 16, ga + 8);
        const __half* gb = &g_W3T[(size_t)(bn + prow) * 512 + kt + kseg];
        const uint32_t sb = stg + 128 * LDT + prow * LDT + kseg * 2;
        cp16(sb, gb);
        cp16(sb + 16, gb + 8);
        CP_COMMIT();
    };

    float acc[2][8][4];
#pragma unroll
    for (int i = 0; i < 2; ++i)
#pragma unroll
        for (int j = 0; j < 8; ++j)
#pragma unroll
            for (int q = 0; q < 4; ++q) acc[i][j][q] = 0.f;

    issue(0);
    issue(1);

#pragma unroll 1
    for (int c = 0; c < NCH; ++c) {
        CP_WAIT1();
        __syncthreads();
        if (c + 2 < NCH) issue(c + 2);

        const uint32_t abase = su + (c % 3) * M1_STG;
        const uint32_t bbase = abase + 128 * LDT;
#pragma unroll
        for (int ks = 0; ks < 2; ++ks) {
            const int kk = ks * 16;
            uint32_t ah[2][4];
#pragma unroll
            for (int mb = 0; mb < 2; ++mb)
                ldsm4(ah[mb], abase + (uint32_t)((a_row + mb * 16) * LDT + (kk + a_kofs) * 2));
#pragma unroll
            for (int np = 0; np < 4; ++np) {
                uint32_t bh[4];
                ldsm4(bh, bbase + (uint32_t)((b_rbase + np * 16) * LDT + (kk + b_kofs) * 2));
#pragma unroll
                for (int mb = 0; mb < 2; ++mb)
#pragma unroll
                    for (int ns = 0; ns < 2; ++ns)
                        mma_f16(acc[mb][np * 2 + ns], ah[mb], bh[2 * ns], bh[2 * ns + 1]);
            }
        }
    }
    CP_WAIT0();

    const int g   = lane >> 2;
    const int tig = lane & 3;
#pragma unroll
    for (int mb = 0; mb < 2; ++mb)
#pragma unroll
        for (int nb = 0; nb < 8; ++nb) {
            const int col = bn + warpN * 64 + nb * 8 + tig * 2;
            const float bz0 = b3[col], bz1 = b3[col + 1];
            const int rr = bm + warpM * 32 + mb * 16 + g;
            const float* cc = acc[mb][nb];
#pragma unroll
            for (int hf = 0; hf < 2; ++hf) {
                const int r = rr + hf * 8;
                *(float2*)&outf[(size_t)r * H3D + col] =
                    make_float2(fmaxf(cc[2*hf] + bz0, 0.f), fmaxf(cc[2*hf+1] + bz1, 0.f));
            }
        }
}

// ---------------- launch (order: k_mlp2 is 4th -> gets profiled) ----------------
extern "C" void kernel_launch(void* const* d_in, const int* in_sizes, int n_in,
                              void* d_out, int out_size)
{
    const float* inf = (const float*)d_in[0];
    const float* Wd  = (const float*)d_in[1];
    const float* bd  = (const float*)d_in[2];
    const float* W1  = (const float*)d_in[3];
    const float* b1  = (const float*)d_in[4];
    const float* W2  = (const float*)d_in[5];
    const float* b2  = (const float*)d_in[6];
    const float* W3  = (const float*)d_in[7];
    const float* b3  = (const float*)d_in[8];
    float* out = (float*)d_out;

    cudaFuncSetAttribute(k_mlp2, cudaFuncAttributeMaxDynamicSharedMemorySize, M0_SMEM);
    cudaFuncSetAttribute(k_mlp3, cudaFuncAttributeMaxDynamicSharedMemorySize, M1_SMEM);

    k_dec<<<NPAR, 128>>>(inf, Wd, bd, out + RP_OFF);
    k_prep<<<(512 * 512 + 256 * 512) / 256, 256>>>(W2, W3);
    k_f1<<<dim3(NPAR / 128, H1D / 128), 256>>>(inf, W1, b1);
    k_mlp2<<<dim3(NROWS / 128, H2D / 256), 512, M0_SMEM>>>(out + RP_OFF, W1, b2);
    k_cluster<<<NROWS / 256, 256>>>(out + CL_OFF);
    k_mlp3<<<dim3(NROWS / 128, H3D / 128), 256, M1_SMEM>>>(b3, out + H_OFF);
}

// round 12
// speedup vs baseline: 1.3210x; 1.1564x over previous
#include <cuda_runtime.h>
#include <cuda_fp16.h>
#include <cstdint>
#include <cstddef>

// ---------------- problem constants ----------------
#define NPAR   4096
#define KCH    32
#define NEIGHD 128
#define FEATD  256
#define NROWS  (NPAR * KCH)        // 131072
#define H1D    512
#define H2D    512
#define H3D    256
#define INSTR  (NEIGHD + FEATD)    // 384

// output layout: [relative_points (NROWS*3) | h (NROWS*256) | cluster (NROWS)]
#define RP_OFF 0
#define H_OFF  ((size_t)NROWS * 3)
#define CL_OFF (H_OFF + (size_t)NROWS * H3D)

// ---------------- scratch (device globals) ----------------
__device__ float  g_F1[(size_t)NPAR * H1D];      // fp32, 8 MB
__device__ __half g_H2h[(size_t)NROWS * H2D];    // h2 fp16, 128 MB
__device__ __half g_W2T[512 * 512];              // W2^T fp16 [n][k]
__device__ __half g_W3T[256 * 512];              // W3^T fp16 [n][k]

// ---------------- helpers ----------------
__device__ __forceinline__ uint32_t smem_u32(const void* p) {
    uint32_t a;
    asm("{ .reg .u64 t; cvta.to.shared.u64 t, %1; cvt.u32.u64 %0, t; }" : "=r"(a) : "l"(p));
    return a;
}
__device__ __forceinline__ void ldsm4(uint32_t r[4], uint32_t addr) {
    asm volatile("ldmatrix.sync.aligned.m8n8.x4.shared.b16 {%0,%1,%2,%3}, [%4];"
                 : "=r"(r[0]), "=r"(r[1]), "=r"(r[2]), "=r"(r[3]) : "r"(addr));
}
__device__ __forceinline__ void mma_f16(float c[4], const uint32_t a[4],
                                        uint32_t b0, uint32_t b1) {
    asm volatile("mma.sync.aligned.m16n8k16.row.col.f32.f16.f16.f32 "
                 "{%0,%1,%2,%3}, {%4,%5,%6,%7}, {%8,%9}, {%0,%1,%2,%3};"
                 : "+f"(c[0]), "+f"(c[1]), "+f"(c[2]), "+f"(c[3])
                 : "r"(a[0]), "r"(a[1]), "r"(a[2]), "r"(a[3]), "r"(b0), "r"(b1));
}
__device__ __forceinline__ void cp16(uint32_t s, const void* g) {
    asm volatile("cp.async.cg.shared.global [%0], [%1], 16;" :: "r"(s), "l"(g));
}
#define CP_COMMIT() asm volatile("cp.async.commit_group;" ::: "memory")
#define CP_WAIT2()  asm volatile("cp.async.wait_group 2;" ::: "memory")
#define CP_WAIT1()  asm volatile("cp.async.wait_group 1;" ::: "memory")
#define CP_WAIT0()  asm volatile("cp.async.wait_group 0;" ::: "memory")

// ---------------- common tiling ----------------
#define KC    32
#define NCH   (H1D / KC)      // 16 chunks
#define LDT   80              // 32 halves = 64B padded to 80B; conflict-free ldsm
#define NSTG  4               // cp.async ring stages (prefetch depth 3)

// k_mlp2 (L2) layout: 512 threads, CTA 128x256, occ 1 (reg-bound).
#define M0_ABUF   (128 * LDT)                  // 10240
#define M0_BSTG   (256 * LDT)                  // 20480
#define M0_OFF_A  0                            // 2 bufs: 20480
#define M0_OFF_B  (2 * M0_ABUF)                // 20480
#define M0_OFF_W1 (M0_OFF_B + NSTG * M0_BSTG)  // 102400 (6144 B)
#define M0_OFF_RP (M0_OFF_W1 + 6144)           // 108544 (1536 B)
#define M0_SMEM   (M0_OFF_RP + 1536)           // 110080

// k_mlp3 (L3) layout: 256 threads, CTA 128x128, occ 2.
#define M1_STG    (2 * 128 * LDT)              // 20480
#define M1_SMEM   (NSTG * M1_STG)              // 81920

// ---------------- kernel: decoder GEMM ----------------
__global__ void k_dec(const float* __restrict__ inf, const float* __restrict__ Wd,
                      const float* __restrict__ bd, float* __restrict__ out_rp)
{
    __shared__ float s[NEIGHD];
    const int p = blockIdx.x;
    const int t = threadIdx.x;
    s[t] = inf[(size_t)p * INSTR + t];
    __syncthreads();
    if (t < 96) {
        float acc = bd[t];
#pragma unroll 8
        for (int k = 0; k < NEIGHD; ++k)
            acc = fmaf(s[k], Wd[k * 96 + t], acc);
        out_rp[(size_t)p * 96 + t] = acc;
    }
}

// ---------------- kernel: merged weight transpose + fp16 prep ----------------
__global__ void k_prep(const float* __restrict__ W2, const float* __restrict__ W3)
{
    const int idx = blockIdx.x * 256 + threadIdx.x;
    if (idx < 512 * 512) {
        const int n = idx >> 9, k = idx & 511;
        g_W2T[idx] = __float2half(W2[(size_t)k * H2D + n]);
    } else {
        const int i2 = idx - 512 * 512;
        const int n = i2 >> 9, k = i2 & 511;
        g_W3T[i2] = __float2half(W3[(size_t)k * H3D + n]);
    }
}

// ---------------- kernel: F1 = features @ W1[0:256,:] + b1 (fp32 SIMT) ----
__global__ void k_f1(const float* __restrict__ inf, const float* __restrict__ W1,
                     const float* __restrict__ b1)
{
    __shared__ float As[16 * 132];
    __shared__ float Bs[16 * 128];
    const int tid  = threadIdx.x;
    const int bm   = blockIdx.x * 128;
    const int bn   = blockIdx.y * 128;
    const int arow = tid >> 2;
    const int acol = (tid & 3) * 4;
    const int brow = tid >> 5;
    const int bcol = (tid & 31) * 4;
    const int tr   = (tid >> 4) * 8;
    const int tc   = (tid & 15) * 8;

    float acc[8][8];
#pragma unroll
    for (int i = 0; i < 8; ++i)
#pragma unroll
        for (int j = 0; j < 8; ++j) acc[i][j] = 0.f;

    for (int kt = 0; kt < FEATD; kt += 16) {
#pragma unroll
        for (int s = 0; s < 2; ++s) {
            const int m = arow + s * 64;
            const float4 av = *(const float4*)&inf[(size_t)(bm + m) * INSTR + NEIGHD + kt + acol];
            As[(acol + 0) * 132 + m] = av.x;
            As[(acol + 1) * 132 + m] = av.y;
            As[(acol + 2) * 132 + m] = av.z;
            As[(acol + 3) * 132 + m] = av.w;
        }
#pragma unroll
        for (int s = 0; s < 2; ++s) {
            const int k = brow + s * 8;
            *(float4*)&Bs[k * 128 + bcol] =
                *(const float4*)&W1[(size_t)(kt + k) * H1D + bn + bcol];
        }
        __syncthreads();
#pragma unroll
        for (int k = 0; k < 16; ++k) {
            const float4 a0 = *(const float4*)&As[k * 132 + tr];
            const float4 a1 = *(const float4*)&As[k * 132 + tr + 4];
            const float4 b0 = *(const float4*)&Bs[k * 128 + tc];
            const float4 b1v = *(const float4*)&Bs[k * 128 + tc + 4];
            const float am[8] = {a0.x, a0.y, a0.z, a0.w, a1.x, a1.y, a1.z, a1.w};
            const float bnv[8] = {b0.x, b0.y, b0.z, b0.w, b1v.x, b1v.y, b1v.z, b1v.w};
#pragma unroll
            for (int i = 0; i < 8; ++i)
#pragma unroll
                for (int j = 0; j < 8; ++j)
                    acc[i][j] = fmaf(am[i], bnv[j], acc[i][j]);
        }
        __syncthreads();
    }
#pragma unroll
    for (int i = 0; i < 8; ++i) {
        const size_t row = (size_t)(bm + tr + i);
#pragma unroll
        for (int j = 0; j < 8; ++j)
            g_F1[row * H1D + bn + tc + j] = acc[i][j] + b1[bn + tc + j];
    }
}

// ---------------- kernel: cluster indices ----------------
__global__ void k_cluster(float* __restrict__ out_cl)
{
    const int i = blockIdx.x * blockDim.x + threadIdx.x;
    if (i < NROWS) out_cl[i] = (float)(i >> 5);
}

// =======================================================================
// L2 GEMM (h2 = relu(h1 @ W2T + b2)): CTA 128x256, 512 threads, occ 1.
// A = relu(F1[parent] + rp.W1tail) fp16, F1 prefetched to regs 2 chunks
// ahead, w1t read as float4 (6 LDS.128/thread/chunk, was 24 LDS.32).
// B = W2T via cp.async 4-stage ring, prefetch depth 3.
// 16 warps: warpM = wid&3 (32 rows), warpN = wid>>2 (64 cols).
// =======================================================================
__global__ void __launch_bounds__(512, 1) k_mlp2(
    const float* __restrict__ rp, const float* __restrict__ W1,
    const float* __restrict__ b2)
{
    extern __shared__ char smem[];
    const uint32_t su = smem_u32(smem);
    const int tid  = threadIdx.x;
    const int wid  = tid >> 5;
    const int lane = tid & 31;
    const int bm   = blockIdx.x * 128;
    const int bn   = blockIdx.y * 256;

    float* w1t = (float*)(smem + M0_OFF_W1);
    float* rps = (float*)(smem + M0_OFF_RP);
    for (int i = tid; i < 3 * H1D; i += 512)
        w1t[i] = W1[(size_t)(FEATD + i / H1D) * H1D + (i % H1D)];
    for (int i = tid; i < 128 * 3; i += 512)
        rps[i] = rp[(size_t)bm * 3 + i];
    __syncthreads();

    const int warpM = wid & 3;
    const int warpN = wid >> 2;
    const int a_row   = warpM * 32 + (lane & 15);
    const int a_kofs  = (lane >> 4) * 8;
    const int b_rbase = warpN * 64 + (lane & 7) + ((lane >> 4) << 3);
    const int b_kofs  = ((lane >> 3) & 1) * 8;

    // A staging: 128 rows x 32 k, 8 elems/thread
    const int prow = tid >> 2;            // 0..127
    const int pc0  = (tid & 3) * 8;       // 0,8,16,24
    const int parent = (bm + prow) >> 5;
    const float r0 = rps[prow * 3 + 0];
    const float r1 = rps[prow * 3 + 1];
    const float r2 = rps[prow * 3 + 2];

    // B staging: 256 rows x 32 k, 16 halves/thread (2 cp16)
    const int brow = tid >> 1;            // 0..255
    const int kseg = (tid & 1) * 16;      // 0 or 16 halves

    float pf[8];   // prefetched F1 for A chunk

    auto fetchA = [&](int c) {
        const float* f = &g_F1[(size_t)parent * H1D + c * KC + pc0];
        *(float4*)&pf[0] = *(const float4*)f;
        *(float4*)&pf[4] = *(const float4*)(f + 4);
    };
    auto stageA = [&](int c, int buf) {
        const int ktk = c * KC + pc0;     // multiple of 8 -> float4 aligned
        uint32_t uh[4];
#pragma unroll
        for (int grp = 0; grp < 2; ++grp) {
            const int k = ktk + grp * 4;
            const float4 wa = *(const float4*)&w1t[k];
            const float4 wb = *(const float4*)&w1t[512 + k];
            const float4 wc = *(const float4*)&w1t[1024 + k];
            const float v0 = fmaxf(pf[4*grp+0] + r0 * wa.x + r1 * wb.x + r2 * wc.x, 0.f);
            const float v1 = fmaxf(pf[4*grp+1] + r0 * wa.y + r1 * wb.y + r2 * wc.y, 0.f);
            const float v2 = fmaxf(pf[4*grp+2] + r0 * wa.z + r1 * wb.z + r2 * wc.z, 0.f);
            const float v3 = fmaxf(pf[4*grp+3] + r0 * wa.w + r1 * wb.w + r2 * wc.w, 0.f);
            const __half2 ha = __floats2half2_rn(v0, v1);
            const __half2 hb = __floats2half2_rn(v2, v3);
            uh[grp * 2 + 0] = *(const uint32_t*)&ha;
            uh[grp * 2 + 1] = *(const uint32_t*)&hb;
        }
        *(uint4*)(smem + M0_OFF_A + buf * M0_ABUF + prow * LDT + pc0 * 2) =
            make_uint4(uh[0], uh[1], uh[2], uh[3]);
    };
    auto issueB = [&](int c) {
        const __half* g = &g_W2T[(size_t)(bn + brow) * 512 + c * KC + kseg];
        const uint32_t s = su + M0_OFF_B + (c % NSTG) * M0_BSTG + brow * LDT + kseg * 2;
        cp16(s, g);
        cp16(s + 16, g + 8);
        CP_COMMIT();
    };

    float acc[2][8][4];
#pragma unroll
    for (int i = 0; i < 2; ++i)
#pragma unroll
        for (int j = 0; j < 8; ++j)
#pragma unroll
            for (int q = 0; q < 4; ++q) acc[i][j][q] = 0.f;

    // prologue
    fetchA(0);
    stageA(0, 0);
    fetchA(1);
    issueB(0);
    issueB(1);
    issueB(2);

#pragma unroll 1
    for (int c = 0; c < NCH; ++c) {
        if (c + 2 < NCH)      { CP_WAIT2(); }
        else if (c + 1 < NCH) { CP_WAIT1(); }
        else                  { CP_WAIT0(); }
        __syncthreads();                    // B(c) landed, A buf(c&1) visible
        if (c + 3 < NCH) issueB(c + 3);

        const uint32_t abase = su + M0_OFF_A + (c & 1) * M0_ABUF;
        const uint32_t bbase = su + M0_OFF_B + (c % NSTG) * M0_BSTG;
#pragma unroll
        for (int ks = 0; ks < 2; ++ks) {
            const int kk = ks * 16;
            uint32_t ah[2][4];
#pragma unroll
            for (int mb = 0; mb < 2; ++mb)
                ldsm4(ah[mb], abase + (uint32_t)((a_row + mb * 16) * LDT + (kk + a_kofs) * 2));
#pragma unroll
            for (int np = 0; np < 4; ++np) {
                uint32_t bh[4];
                ldsm4(bh, bbase + (uint32_t)((b_rbase + np * 16) * LDT + (kk + b_kofs) * 2));
#pragma unroll
                for (int mb = 0; mb < 2; ++mb)
#pragma unroll
                    for (int ns = 0; ns < 2; ++ns)
                        mma_f16(acc[mb][np * 2 + ns], ah[mb], bh[2 * ns], bh[2 * ns + 1]);
            }
        }
        if (c + 1 < NCH) {
            stageA(c + 1, (c + 1) & 1);
            if (c + 2 < NCH) fetchA(c + 2);
        }
    }
    CP_WAIT0();

    // epilogue -> g_H2h fp16
    const int g   = lane >> 2;
    const int tig = lane & 3;
#pragma unroll
    for (int mb = 0; mb < 2; ++mb)
#pragma unroll
        for (int nb = 0; nb < 8; ++nb) {
            const int col = bn + warpN * 64 + nb * 8 + tig * 2;
            const float bz0 = b2[col], bz1 = b2[col + 1];
            const int rr = bm + warpM * 32 + mb * 16 + g;
            const float* cc = acc[mb][nb];
#pragma unroll
            for (int hf = 0; hf < 2; ++hf) {
                const int r = rr + hf * 8;
                *(__half2*)&g_H2h[(size_t)r * H2D + col] =
                    __halves2half2(__float2half(fmaxf(cc[2*hf] + bz0, 0.f)),
                                   __float2half(fmaxf(cc[2*hf+1] + bz1, 0.f)));
            }
        }
}

// =======================================================================
// L3 GEMM (h = relu(h2 @ W3T + b3)): CTA 128x128, 256 threads, occ 2.
// A (g_H2h) and B (g_W3T) both via cp.async 4-stage ring, depth 3.
// =======================================================================
__global__ void __launch_bounds__(256, 2) k_mlp3(
    const float* __restrict__ b3, float* __restrict__ outf)
{
    extern __shared__ char smem[];
    const uint32_t su = smem_u32(smem);
    const int tid  = threadIdx.x;
    const int wid  = tid >> 5;
    const int lane = tid & 31;
    const int bm   = blockIdx.x * 128;
    const int bn   = blockIdx.y * 128;

    const int warpM = wid & 3;
    const int warpN = wid >> 2;
    const int a_row   = warpM * 32 + (lane & 15);
    const int a_kofs  = (lane >> 4) * 8;
    const int b_rbase = warpN * 64 + (lane & 7) + ((lane >> 4) << 3);
    const int b_kofs  = ((lane >> 3) & 1) * 8;

    const int prow = tid >> 1;
    const int kseg = (tid & 1) * 16;

    auto issue = [&](int c) {
        const int kt = c * KC;
        const uint32_t stg = su + (c % NSTG) * M1_STG;
        const __half* ga = &g_H2h[(size_t)(bm + prow) * H2D + kt + kseg];
        const uint32_t sa = stg + prow * LDT + kseg * 2;
        cp16(sa, ga);
        cp16(sa + 16, ga + 8);
        const __half* gb = &g_W3T[(size_t)(bn + prow) * 512 + kt + kseg];
        const uint32_t sb = stg + 128 * LDT + prow * LDT + kseg * 2;
        cp16(sb, gb);
        cp16(sb + 16, gb + 8);
        CP_COMMIT();
    };

    float acc[2][8][4];
#pragma unroll
    for (int i = 0; i < 2; ++i)
#pragma unroll
        for (int j = 0; j < 8; ++j)
#pragma unroll
            for (int q = 0; q < 4; ++q) acc[i][j][q] = 0.f;

    issue(0);
    issue(1);
    issue(2);

#pragma unroll 1
    for (int c = 0; c < NCH; ++c) {
        if (c + 2 < NCH)      { CP_WAIT2(); }
        else if (c + 1 < NCH) { CP_WAIT1(); }
        else                  { CP_WAIT0(); }
        __syncthreads();
        if (c + 3 < NCH) issue(c + 3);

        const uint32_t abase = su + (c % NSTG) * M1_STG;
        const uint32_t bbase = abase + 128 * LDT;
#pragma unroll
        for (int ks = 0; ks < 2; ++ks) {
            const int kk = ks * 16;
            uint32_t ah[2][4];
#pragma unroll
            for (int mb = 0; mb < 2; ++mb)
                ldsm4(ah[mb], abase + (uint32_t)((a_row + mb * 16) * LDT + (kk + a_kofs) * 2));
#pragma unroll
            for (int np = 0; np < 4; ++np) {
                uint32_t bh[4];
                ldsm4(bh, bbase + (uint32_t)((b_rbase + np * 16) * LDT + (kk + b_kofs) * 2));
#pragma unroll
                for (int mb = 0; mb < 2; ++mb)
#pragma unroll
                    for (int ns = 0; ns < 2; ++ns)
                        mma_f16(acc[mb][np * 2 + ns], ah[mb], bh[2 * ns], bh[2 * ns + 1]);
            }
        }
    }
    CP_WAIT0();

    const int g   = lane >> 2;
    const int tig = lane & 3;
#pragma unroll
    for (int mb = 0; mb < 2; ++mb)
#pragma unroll
        for (int nb = 0; nb < 8; ++nb) {
            const int col = bn + warpN * 64 + nb * 8 + tig * 2;
            const float bz0 = b3[col], bz1 = b3[col + 1];
            const int rr = bm + warpM * 32 + mb * 16 + g;
            const float* cc = acc[mb][nb];
#pragma unroll
            for (int hf = 0; hf < 2; ++hf) {
                const int r = rr + hf * 8;
                *(float2*)&outf[(size_t)r * H3D + col] =
                    make_float2(fmaxf(cc[2*hf] + bz0, 0.f), fmaxf(cc[2*hf+1] + bz1, 0.f));
            }
        }
}

// ---------------- launch (k_mlp2 in profile slot 4) ----------------
extern "C" void kernel_launch(void* const* d_in, const int* in_sizes, int n_in,
                              void* d_out, int out_size)
{
    const float* inf = (const float*)d_in[0];
    const float* Wd  = (const float*)d_in[1];
    const float* bd  = (const float*)d_in[2];
    const float* W1  = (const float*)d_in[3];
    const float* b1  = (const float*)d_in[4];
    const float* W2  = (const float*)d_in[5];
    const float* b2  = (const float*)d_in[6];
    const float* W3  = (const float*)d_in[7];
    const float* b3  = (const float*)d_in[8];
    float* out = (float*)d_out;

    cudaFuncSetAttribute(k_mlp2, cudaFuncAttributeMaxDynamicSharedMemorySize, M0_SMEM);
    cudaFuncSetAttribute(k_mlp3, cudaFuncAttributeMaxDynamicSharedMemorySize, M1_SMEM);

    k_dec<<<NPAR, 128>>>(inf, Wd, bd, out + RP_OFF);
    k_prep<<<(512 * 512 + 256 * 512) / 256, 256>>>(W2, W3);
    k_f1<<<dim3(NPAR / 128, H1D / 128), 256>>>(inf, W1, b1);
    k_mlp2<<<dim3(NROWS / 128, H2D / 256), 512, M0_SMEM>>>(out + RP_OFF, W1, b2);
    k_cluster<<<NROWS / 256, 256>>>(out + CL_OFF);
    k_mlp3<<<dim3(NROWS / 128, H3D / 128), 256, M1_SMEM>>>(b3, out + H_OFF);
}

// round 13
// speedup vs baseline: 1.3252x; 1.0032x over previous
#include <cuda_runtime.h>
#include <cuda_fp16.h>
#include <cstdint>
#include <cstddef>

// ---------------- problem constants ----------------
#define NPAR   4096
#define KCH    32
#define NEIGHD 128
#define FEATD  256
#define NROWS  (NPAR * KCH)        // 131072
#define H1D    512
#define H2D    512
#define H3D    256
#define INSTR  (NEIGHD + FEATD)    // 384

// output layout: [relative_points (NROWS*3) | h (NROWS*256) | cluster (NROWS)]
#define RP_OFF 0
#define H_OFF  ((size_t)NROWS * 3)
#define CL_OFF (H_OFF + (size_t)NROWS * H3D)

// ---------------- scratch (device globals) ----------------
__device__ float  g_F1[(size_t)NPAR * H1D];      // fp32, 8 MB
__device__ __half g_H2h[(size_t)NROWS * H2D];    // h2 fp16, 128 MB
__device__ __half g_W2T[512 * 512];              // W2^T fp16 [n][k]
__device__ __half g_W3T[256 * 512];              // W3^T fp16 [n][k]

// ---------------- helpers ----------------
__device__ __forceinline__ uint32_t smem_u32(const void* p) {
    uint32_t a;
    asm("{ .reg .u64 t; cvta.to.shared.u64 t, %1; cvt.u32.u64 %0, t; }" : "=r"(a) : "l"(p));
    return a;
}
__device__ __forceinline__ void ldsm4(uint32_t r[4], uint32_t addr) {
    asm volatile("ldmatrix.sync.aligned.m8n8.x4.shared.b16 {%0,%1,%2,%3}, [%4];"
                 : "=r"(r[0]), "=r"(r[1]), "=r"(r[2]), "=r"(r[3]) : "r"(addr));
}
__device__ __forceinline__ void mma_f16(float c[4], const uint32_t a[4],
                                        uint32_t b0, uint32_t b1) {
    asm volatile("mma.sync.aligned.m16n8k16.row.col.f32.f16.f16.f32 "
                 "{%0,%1,%2,%3}, {%4,%5,%6,%7}, {%8,%9}, {%0,%1,%2,%3};"
                 : "+f"(c[0]), "+f"(c[1]), "+f"(c[2]), "+f"(c[3])
                 : "r"(a[0]), "r"(a[1]), "r"(a[2]), "r"(a[3]), "r"(b0), "r"(b1));
}
__device__ __forceinline__ void cp16(uint32_t s, const void* g) {
    asm volatile("cp.async.cg.shared.global [%0], [%1], 16;" :: "r"(s), "l"(g));
}
#define CP_COMMIT() asm volatile("cp.async.commit_group;" ::: "memory")
#define CP_WAIT2()  asm volatile("cp.async.wait_group 2;" ::: "memory")
#define CP_WAIT1()  asm volatile("cp.async.wait_group 1;" ::: "memory")
#define CP_WAIT0()  asm volatile("cp.async.wait_group 0;" ::: "memory")

// ---------------- common tiling ----------------
#define KC    32
#define NCH   (H1D / KC)      // 16 chunks
#define LDT   80              // 32 halves = 64B padded to 80B; conflict-free ldsm
#define NSTG  4               // cp.async ring stages (prefetch depth 3)

// k_mlp2 (L2) layout: 512 threads, CTA 128x256, occ 1 (reg-bound).
#define M0_ABUF   (128 * LDT)                  // 10240
#define M0_BSTG   (256 * LDT)                  // 20480
#define M0_OFF_A  0                            // 2 bufs: 20480
#define M0_OFF_B  (2 * M0_ABUF)                // 20480
#define M0_OFF_W1 (M0_OFF_B + NSTG * M0_BSTG)  // 102400 (6144 B)
#define M0_OFF_RP (M0_OFF_W1 + 6144)           // 108544 (1536 B)
#define M0_SMEM   (M0_OFF_RP + 1536)           // 110080

// k_mlp3 (L3) layout: 256 threads, CTA 128x128, occ 2.
#define M1_STG    (2 * 128 * LDT)              // 20480
#define M1_SMEM   (NSTG * M1_STG)              // 81920

// ---------------- kernel: decoder GEMM ----------------
__global__ void k_dec(const float* __restrict__ inf, const float* __restrict__ Wd,
                      const float* __restrict__ bd, float* __restrict__ out_rp)
{
    __shared__ float s[NEIGHD];
    const int p = blockIdx.x;
    const int t = threadIdx.x;
    s[t] = inf[(size_t)p * INSTR + t];
    __syncthreads();
    if (t < 96) {
        float acc = bd[t];
#pragma unroll 8
        for (int k = 0; k < NEIGHD; ++k)
            acc = fmaf(s[k], Wd[k * 96 + t], acc);
        out_rp[(size_t)p * 96 + t] = acc;
    }
}

// ---------------- kernel: merged weight transpose + fp16 prep ----------------
__global__ void k_prep(const float* __restrict__ W2, const float* __restrict__ W3)
{
    const int idx = blockIdx.x * 256 + threadIdx.x;
    if (idx < 512 * 512) {
        const int n = idx >> 9, k = idx & 511;
        g_W2T[idx] = __float2half(W2[(size_t)k * H2D + n]);
    } else {
        const int i2 = idx - 512 * 512;
        const int n = i2 >> 9, k = i2 & 511;
        g_W3T[i2] = __float2half(W3[(size_t)k * H3D + n]);
    }
}

// ---------------- kernel: F1 = features @ W1[0:256,:] + b1 (fp32 SIMT) ----
__global__ void k_f1(const float* __restrict__ inf, const float* __restrict__ W1,
                     const float* __restrict__ b1)
{
    __shared__ float As[16 * 132];
    __shared__ float Bs[16 * 128];
    const int tid  = threadIdx.x;
    const int bm   = blockIdx.x * 128;
    const int bn   = blockIdx.y * 128;
    const int arow = tid >> 2;
    const int acol = (tid & 3) * 4;
    const int brow = tid >> 5;
    const int bcol = (tid & 31) * 4;
    const int tr   = (tid >> 4) * 8;
    const int tc   = (tid & 15) * 8;

    float acc[8][8];
#pragma unroll
    for (int i = 0; i < 8; ++i)
#pragma unroll
        for (int j = 0; j < 8; ++j) acc[i][j] = 0.f;

    for (int kt = 0; kt < FEATD; kt += 16) {
#pragma unroll
        for (int s = 0; s < 2; ++s) {
            const int m = arow + s * 64;
            const float4 av = *(const float4*)&inf[(size_t)(bm + m) * INSTR + NEIGHD + kt + acol];
            As[(acol + 0) * 132 + m] = av.x;
            As[(acol + 1) * 132 + m] = av.y;
            As[(acol + 2) * 132 + m] = av.z;
            As[(acol + 3) * 132 + m] = av.w;
        }
#pragma unroll
        for (int s = 0; s < 2; ++s) {
            const int k = brow + s * 8;
            *(float4*)&Bs[k * 128 + bcol] =
                *(const float4*)&W1[(size_t)(kt + k) * H1D + bn + bcol];
        }
        __syncthreads();
#pragma unroll
        for (int k = 0; k < 16; ++k) {
            const float4 a0 = *(const float4*)&As[k * 132 + tr];
            const float4 a1 = *(const float4*)&As[k * 132 + tr + 4];
            const float4 b0 = *(const float4*)&Bs[k * 128 + tc];
            const float4 b1v = *(const float4*)&Bs[k * 128 + tc + 4];
            const float am[8] = {a0.x, a0.y, a0.z, a0.w, a1.x, a1.y, a1.z, a1.w};
            const float bnv[8] = {b0.x, b0.y, b0.z, b0.w, b1v.x, b1v.y, b1v.z, b1v.w};
#pragma unroll
            for (int i = 0; i < 8; ++i)
#pragma unroll
                for (int j = 0; j < 8; ++j)
                    acc[i][j] = fmaf(am[i], bnv[j], acc[i][j]);
        }
        __syncthreads();
    }
#pragma unroll
    for (int i = 0; i < 8; ++i) {
        const size_t row = (size_t)(bm + tr + i);
#pragma unroll
        for (int j = 0; j < 8; ++j)
            g_F1[row * H1D + bn + tc + j] = acc[i][j] + b1[bn + tc + j];
    }
}

// ---------------- kernel: cluster indices ----------------
__global__ void k_cluster(float* __restrict__ out_cl)
{
    const int i = blockIdx.x * blockDim.x + threadIdx.x;
    if (i < NROWS) out_cl[i] = (float)(i >> 5);
}

// =======================================================================
// L2 GEMM (h2 = relu(h1 @ W2T + b2)): CTA 128x256, 512 threads, occ 1.
// A = relu(F1[parent] + rp.W1tail) fp16, F1 prefetched to regs 2 chunks
// ahead, w1t read as float4 (6 LDS.128/thread/chunk, was 24 LDS.32).
// B = W2T via cp.async 4-stage ring, prefetch depth 3.
// 16 warps: warpM = wid&3 (32 rows), warpN = wid>>2 (64 cols).
// =======================================================================
__global__ void __launch_bounds__(512, 1) k_mlp2(
    const float* __restrict__ rp, const float* __restrict__ W1,
    const float* __restrict__ b2)
{
    extern __shared__ char smem[];
    const uint32_t su = smem_u32(smem);
    const int tid  = threadIdx.x;
    const int wid  = tid >> 5;
    const int lane = tid & 31;
    const int bm   = blockIdx.x * 128;
    const int bn   = blockIdx.y * 256;

    float* w1t = (float*)(smem + M0_OFF_W1);
    float* rps = (float*)(smem + M0_OFF_RP);
    for (int i = tid; i < 3 * H1D; i += 512)
        w1t[i] = W1[(size_t)(FEATD + i / H1D) * H1D + (i % H1D)];
    for (int i = tid; i < 128 * 3; i += 512)
        rps[i] = rp[(size_t)bm * 3 + i];
    __syncthreads();

    const int warpM = wid & 3;
    const int warpN = wid >> 2;
    const int a_row   = warpM * 32 + (lane & 15);
    const int a_kofs  = (lane >> 4) * 8;
    const int b_rbase = warpN * 64 + (lane & 7) + ((lane >> 4) << 3);
    const int b_kofs  = ((lane >> 3) & 1) * 8;

    // A staging: 128 rows x 32 k, 8 elems/thread
    const int prow = tid >> 2;            // 0..127
    const int pc0  = (tid & 3) * 8;       // 0,8,16,24
    const int parent = (bm + prow) >> 5;
    const float r0 = rps[prow * 3 + 0];
    const float r1 = rps[prow * 3 + 1];
    const float r2 = rps[prow * 3 + 2];

    // B staging: 256 rows x 32 k, 16 halves/thread (2 cp16)
    const int brow = tid >> 1;            // 0..255
    const int kseg = (tid & 1) * 16;      // 0 or 16 halves

    float pf[8];   // prefetched F1 for A chunk

    auto fetchA = [&](int c) {
        const float* f = &g_F1[(size_t)parent * H1D + c * KC + pc0];
        *(float4*)&pf[0] = *(const float4*)f;
        *(float4*)&pf[4] = *(const float4*)(f + 4);
    };
    auto stageA = [&](int c, int buf) {
        const int ktk = c * KC + pc0;     // multiple of 8 -> float4 aligned
        uint32_t uh[4];
#pragma unroll
        for (int grp = 0; grp < 2; ++grp) {
            const int k = ktk + grp * 4;
            const float4 wa = *(const float4*)&w1t[k];
            const float4 wb = *(const float4*)&w1t[512 + k];
            const float4 wc = *(const float4*)&w1t[1024 + k];
            const float v0 = fmaxf(pf[4*grp+0] + r0 * wa.x + r1 * wb.x + r2 * wc.x, 0.f);
            const float v1 = fmaxf(pf[4*grp+1] + r0 * wa.y + r1 * wb.y + r2 * wc.y, 0.f);
            const float v2 = fmaxf(pf[4*grp+2] + r0 * wa.z + r1 * wb.z + r2 * wc.z, 0.f);
            const float v3 = fmaxf(pf[4*grp+3] + r0 * wa.w + r1 * wb.w + r2 * wc.w, 0.f);
            const __half2 ha = __floats2half2_rn(v0, v1);
            const __half2 hb = __floats2half2_rn(v2, v3);
            uh[grp * 2 + 0] = *(const uint32_t*)&ha;
            uh[grp * 2 + 1] = *(const uint32_t*)&hb;
        }
        *(uint4*)(smem + M0_OFF_A + buf * M0_ABUF + prow * LDT + pc0 * 2) =
            make_uint4(uh[0], uh[1], uh[2], uh[3]);
    };
    auto issueB = [&](int c) {
        const __half* g = &g_W2T[(size_t)(bn + brow) * 512 + c * KC + kseg];
        const uint32_t s = su + M0_OFF_B + (c % NSTG) * M0_BSTG + brow * LDT + kseg * 2;
        cp16(s, g);
        cp16(s + 16, g + 8);
        CP_COMMIT();
    };

    float acc[2][8][4];
#pragma unroll
    for (int i = 0; i < 2; ++i)
#pragma unroll
        for (int j = 0; j < 8; ++j)
#pragma unroll
            for (int q = 0; q < 4; ++q) acc[i][j][q] = 0.f;

    // prologue
    fetchA(0);
    stageA(0, 0);
    fetchA(1);
    issueB(0);
    issueB(1);
    issueB(2);

#pragma unroll 1
    for (int c = 0; c < NCH; ++c) {
        if (c + 2 < NCH)      { CP_WAIT2(); }
        else if (c + 1 < NCH) { CP_WAIT1(); }
        else                  { CP_WAIT0(); }
        __syncthreads();                    // B(c) landed, A buf(c&1) visible
        if (c + 3 < NCH) issueB(c + 3);

        const uint32_t abase = su + M0_OFF_A + (c & 1) * M0_ABUF;
        const uint32_t bbase = su + M0_OFF_B + (c % NSTG) * M0_BSTG;
#pragma unroll
        for (int ks = 0; ks < 2; ++ks) {
            const int kk = ks * 16;
            uint32_t ah[2][4];
#pragma unroll
            for (int mb = 0; mb < 2; ++mb)
                ldsm4(ah[mb], abase + (uint32_t)((a_row + mb * 16) * LDT + (kk + a_kofs) * 2));
#pragma unroll
            for (int np = 0; np < 4; ++np) {
                uint32_t bh[4];
                ldsm4(bh, bbase + (uint32_t)((b_rbase + np * 16) * LDT + (kk + b_kofs) * 2));
#pragma unroll
                for (int mb = 0; mb < 2; ++mb)
#pragma unroll
                    for (int ns = 0; ns < 2; ++ns)
                        mma_f16(acc[mb][np * 2 + ns], ah[mb], bh[2 * ns], bh[2 * ns + 1]);
            }
        }
        if (c + 1 < NCH) {
            stageA(c + 1, (c + 1) & 1);
            if (c + 2 < NCH) fetchA(c + 2);
        }
    }
    CP_WAIT0();

    // epilogue -> g_H2h fp16
    const int g   = lane >> 2;
    const int tig = lane & 3;
#pragma unroll
    for (int mb = 0; mb < 2; ++mb)
#pragma unroll
        for (int nb = 0; nb < 8; ++nb) {
            const int col = bn + warpN * 64 + nb * 8 + tig * 2;
            const float bz0 = b2[col], bz1 = b2[col + 1];
            const int rr = bm + warpM * 32 + mb * 16 + g;
            const float* cc = acc[mb][nb];
#pragma unroll
            for (int hf = 0; hf < 2; ++hf) {
                const int r = rr + hf * 8;
                *(__half2*)&g_H2h[(size_t)r * H2D + col] =
                    __halves2half2(__float2half(fmaxf(cc[2*hf] + bz0, 0.f)),
                                   __float2half(fmaxf(cc[2*hf+1] + bz1, 0.f)));
            }
        }
}

// =======================================================================
// L3 GEMM (h = relu(h2 @ W3T + b3)): CTA 128x128, 256 threads, occ 2.
// A (g_H2h) and B (g_W3T) both via cp.async 4-stage ring, depth 3.
// =======================================================================
__global__ void __launch_bounds__(256, 2) k_mlp3(
    const float* __restrict__ b3, float* __restrict__ outf)
{
    extern __shared__ char smem[];
    const uint32_t su = smem_u32(smem);
    const int tid  = threadIdx.x;
    const int wid  = tid >> 5;
    const int lane = tid & 31;
    const int bm   = blockIdx.x * 128;
    const int bn   = blockIdx.y * 128;

    const int warpM = wid & 3;
    const int warpN = wid >> 2;
    const int a_row   = warpM * 32 + (lane & 15);
    const int a_kofs  = (lane >> 4) * 8;
    const int b_rbase = warpN * 64 + (lane & 7) + ((lane >> 4) << 3);
    const int b_kofs  = ((lane >> 3) & 1) * 8;

    const int prow = tid >> 1;
    const int kseg = (tid & 1) * 16;

    auto issue = [&](int c) {
        const int kt = c * KC;
        const uint32_t stg = su + (c % NSTG) * M1_STG;
        const __half* ga = &g_H2h[(size_t)(bm + prow) * H2D + kt + kseg];
        const uint32_t sa = stg + prow * LDT + kseg * 2;
        cp16(sa, ga);
        cp16(sa + 16, ga + 8);
        const __half* gb = &g_W3T[(size_t)(bn + prow) * 512 + kt + kseg];
        const uint32_t sb = stg + 128 * LDT + prow * LDT + kseg * 2;
        cp16(sb, gb);
        cp16(sb + 16, gb + 8);
        CP_COMMIT();
    };

    float acc[2][8][4];
#pragma unroll
    for (int i = 0; i < 2; ++i)
#pragma unroll
        for (int j = 0; j < 8; ++j)
#pragma unroll
            for (int q = 0; q < 4; ++q) acc[i][j][q] = 0.f;

    issue(0);
    issue(1);
    issue(2);

#pragma unroll 1
    for (int c = 0; c < NCH; ++c) {
        if (c + 2 < NCH)      { CP_WAIT2(); }
        else if (c + 1 < NCH) { CP_WAIT1(); }
        else                  { CP_WAIT0(); }
        __syncthreads();
        if (c + 3 < NCH) issue(c + 3);

        const uint32_t abase = su + (c % NSTG) * M1_STG;
        const uint32_t bbase = abase + 128 * LDT;
#pragma unroll
        for (int ks = 0; ks < 2; ++ks) {
            const int kk = ks * 16;
            uint32_t ah[2][4];
#pragma unroll
            for (int mb = 0; mb < 2; ++mb)
                ldsm4(ah[mb], abase + (uint32_t)((a_row + mb * 16) * LDT + (kk + a_kofs) * 2));
#pragma unroll
            for (int np = 0; np < 4; ++np) {
                uint32_t bh[4];
                ldsm4(bh, bbase + (uint32_t)((b_rbase + np * 16) * LDT + (kk + b_kofs) * 2));
#pragma unroll
                for (int mb = 0; mb < 2; ++mb)
#pragma unroll
                    for (int ns = 0; ns < 2; ++ns)
                        mma_f16(acc[mb][np * 2 + ns], ah[mb], bh[2 * ns], bh[2 * ns + 1]);
            }
        }
    }
    CP_WAIT0();

    const int g   = lane >> 2;
    const int tig = lane & 3;
#pragma unroll
    for (int mb = 0; mb < 2; ++mb)
#pragma unroll
        for (int nb = 0; nb < 8; ++nb) {
            const int col = bn + warpN * 64 + nb * 8 + tig * 2;
            const float bz0 = b3[col], bz1 = b3[col + 1];
            const int rr = bm + warpM * 32 + mb * 16 + g;
            const float* cc = acc[mb][nb];
#pragma unroll
            for (int hf = 0; hf < 2; ++hf) {
                const int r = rr + hf * 8;
                *(float2*)&outf[(size_t)r * H3D + col] =
                    make_float2(fmaxf(cc[2*hf] + bz0, 0.f), fmaxf(cc[2*hf+1] + bz1, 0.f));
            }
        }
}

// ---------------- launch (k_mlp2 in profile slot 4) ----------------
extern "C" void kernel_launch(void* const* d_in, const int* in_sizes, int n_in,
                              void* d_out, int out_size)
{
    const float* inf = (const float*)d_in[0];
    const float* Wd  = (const float*)d_in[1];
    const float* bd  = (const float*)d_in[2];
    const float* W1  = (const float*)d_in[3];
    const float* b1  = (const float*)d_in[4];
    const float* W2  = (const float*)d_in[5];
    const float* b2  = (const float*)d_in[6];
    const float* W3  = (const float*)d_in[7];
    const float* b3  = (const float*)d_in[8];
    float* out = (float*)d_out;

    cudaFuncSetAttribute(k_mlp2, cudaFuncAttributeMaxDynamicSharedMemorySize, M0_SMEM);
    cudaFuncSetAttribute(k_mlp3, cudaFuncAttributeMaxDynamicSharedMemorySize, M1_SMEM);

    k_dec<<<NPAR, 128>>>(inf, Wd, bd, out + RP_OFF);
    k_prep<<<(512 * 512 + 256 * 512) / 256, 256>>>(W2, W3);
    k_f1<<<dim3(NPAR / 128, H1D / 128), 256>>>(inf, W1, b1);
    k_mlp2<<<dim3(NROWS / 128, H2D / 256), 512, M0_SMEM>>>(out + RP_OFF, W1, b2);
    k_cluster<<<NROWS / 256, 256>>>(out + CL_OFF);
    k_mlp3<<<dim3(NROWS / 128, H3D / 128), 256, M1_SMEM>>>(b3, out + H_OFF);
}